// round 3
// baseline (speedup 1.0000x reference)
#include <cuda_runtime.h>

#define BATCH 2
#define NSEQ  2048
#define DIM   1024
#define NH    16
#define HD    64
#define BH    (BATCH * NH)
#define NOUT  3072   // 3 * NH * HD

// Scratch for q/k/v in [b, h, n, d] layout (static device arrays — no allocations).
__device__ float g_q[(size_t)BH * NSEQ * HD];
__device__ float g_k[(size_t)BH * NSEQ * HD];
__device__ float g_v[(size_t)BH * NSEQ * HD];

// ---------------------------------------------------------------------------
// Kernel 1: QKV GEMM. C[4096, 3072] = X[4096, 1024] @ W[1024, 3072]
// 64x64 tile, BK=16, 256 threads, 4x4 per-thread micro-tile.
// Double-buffered smem: prefetch tile t+1 into registers during compute of
// tile t, one __syncthreads per k-step. A tile stored transposed with XOR
// swizzle (col = r ^ ((k>>2)<<2)).
// ---------------------------------------------------------------------------
__global__ __launch_bounds__(256) void qkv_gemm_kernel(
    const float* __restrict__ X, const float* __restrict__ W)
{
    __shared__ float As[2][16][64];
    __shared__ float Bs[2][16][64];

    const int tid = threadIdx.x;
    const int tx = tid & 15;
    const int ty = tid >> 4;
    const int rowBase = blockIdx.y << 6;
    const int colBase = blockIdx.x << 6;

    float acc[4][4];
#pragma unroll
    for (int i = 0; i < 4; i++)
#pragma unroll
        for (int j = 0; j < 4; j++) acc[i][j] = 0.f;

    const int ar  = tid >> 2;          // 0..63 : A row within tile
    const int akq = (tid & 3) << 2;    // 0,4,8,12 : A k-quad
    const int bk  = tid >> 4;          // 0..15 : B k row
    const int bc  = (tid & 15) << 2;   // B col quad
    const int ac  = ar ^ akq;          // swizzled A column (constant per thread)

    const float* Xp = &X[(size_t)(rowBase + ar) * DIM + akq];
    const float* Wp = &W[(size_t)bk * NOUT + colBase + bc];

    // Prologue: load k0 = 0 into buffer 0.
    {
        float4 a = *(const float4*)&Xp[0];
        float4 b = *(const float4*)&Wp[0];
        *(float4*)&Bs[0][bk][bc] = b;
        As[0][akq + 0][ac] = a.x;
        As[0][akq + 1][ac] = a.y;
        As[0][akq + 2][ac] = a.z;
        As[0][akq + 3][ac] = a.w;
    }
    __syncthreads();

    int buf = 0;
    for (int k0 = 0; k0 < DIM; k0 += 16) {
        const bool has_next = (k0 + 16 < DIM);
        float4 an, bn;
        if (has_next) {
            an = *(const float4*)&Xp[k0 + 16];
            bn = *(const float4*)&Wp[(size_t)(k0 + 16) * NOUT];
        }

#pragma unroll
        for (int kk = 0; kk < 16; kk++) {
            const int sw = (kk >> 2) << 2;
            float4 av = *(const float4*)&As[buf][kk][(ty << 2) ^ sw];
            float4 bv = *(const float4*)&Bs[buf][kk][tx << 2];
            float a_[4] = {av.x, av.y, av.z, av.w};
            float b_[4] = {bv.x, bv.y, bv.z, bv.w};
#pragma unroll
            for (int i = 0; i < 4; i++)
#pragma unroll
                for (int j = 0; j < 4; j++) acc[i][j] += a_[i] * b_[j];
        }

        if (has_next) {
            const int nb = buf ^ 1;
            *(float4*)&Bs[nb][bk][bc] = bn;
            As[nb][akq + 0][ac] = an.x;
            As[nb][akq + 1][ac] = an.y;
            As[nb][akq + 2][ac] = an.z;
            As[nb][akq + 3][ac] = an.w;
            __syncthreads();
            buf = nb;
        }
    }

    // Epilogue: scatter into q/k/v with [b,h,n,d] layout. A 64-wide col tile
    // lies entirely within one (section, head) block, so stores coalesce.
    const int col0 = colBase + (tx << 2);
    const int sec  = col0 >> 10;             // 0=q 1=k 2=v
    const int cc   = col0 & 1023;
    const int h    = cc >> 6;
    const int d0   = cc & 63;
    float* dst = (sec == 0) ? g_q : ((sec == 1) ? g_k : g_v);

#pragma unroll
    for (int i = 0; i < 4; i++) {
        const int row = rowBase + (ty << 2) + i;
        const int b = row >> 11;
        const int n = row & (NSEQ - 1);
        float4 v = make_float4(acc[i][0], acc[i][1], acc[i][2], acc[i][3]);
        *(float4*)&dst[(((size_t)(b * NH + h) * NSEQ) + n) * HD + d0] = v;
    }
}

// ---------------------------------------------------------------------------
// Kernel 2: flash attention per (b,h). Br = Bc = 64, 256 threads (16x16),
// 4x4 micro-tiles for both S = Q K^T and O += P V. Online softmax with
// per-row (m, l) replicated across the 16 tx lanes via shfl width-16.
// The 1/sqrt(d) scale is folded into the Q tile at load time.
// P^T is staged into the K buffer (aliased) for the PV GEMM.
// Total static smem = 3 * 64 * 64 * 4 = 48 KB exactly.
// ---------------------------------------------------------------------------
__global__ __launch_bounds__(256) void attn_kernel(float* __restrict__ out)
{
    __shared__ float Qt[64][64];   // Q transposed+swizzled: Qt[d][r ^ sw(d)]
    __shared__ float KPt[64][64];  // K^T (swizzled), then reused for P^T
    __shared__ float Vs[64][64];   // V natural [c][d]

    const int tid = threadIdx.x;
    const int tx = tid & 15;
    const int ty = tid >> 4;
    const int bh = blockIdx.y;
    const int q0 = blockIdx.x << 6;

    const float* qp = g_q + ((size_t)bh * NSEQ + q0) * HD;
    const float* kp = g_k + (size_t)bh * NSEQ * HD;
    const float* vp = g_v + (size_t)bh * NSEQ * HD;

    const float scale = 0.125f;   // 1/sqrt(64)

    // Load Q tile transposed + swizzled, pre-scaled by 1/sqrt(d)
#pragma unroll
    for (int it = 0; it < 4; it++) {
        const int lin = tid + (it << 8);       // 0..1023 float4 slots
        const int r  = lin >> 4;               // 0..63
        const int d0 = (lin & 15) << 2;        // 0..60
        float4 v = *(const float4*)&qp[r * HD + d0];
        const int c = r ^ d0;                  // sw(d0+u) == d0 for u<4
        Qt[d0 + 0][c] = v.x * scale;
        Qt[d0 + 1][c] = v.y * scale;
        Qt[d0 + 2][c] = v.z * scale;
        Qt[d0 + 3][c] = v.w * scale;
    }

    float m[4], l[4], o[4][4];
#pragma unroll
    for (int i = 0; i < 4; i++) {
        m[i] = -1e30f;
        l[i] = 0.f;
#pragma unroll
        for (int j = 0; j < 4; j++) o[i][j] = 0.f;
    }

    for (int t = 0; t < NSEQ / 64; t++) {
        const float* kt = kp + (size_t)t * 64 * HD;
        const float* vt = vp + (size_t)t * 64 * HD;

        // Load K (transposed+swizzled) and V (natural)
#pragma unroll
        for (int it = 0; it < 4; it++) {
            const int lin = tid + (it << 8);
            const int r  = lin >> 4;
            const int d0 = (lin & 15) << 2;
            float4 kv = *(const float4*)&kt[r * HD + d0];
            const int c = r ^ d0;
            KPt[d0 + 0][c] = kv.x;
            KPt[d0 + 1][c] = kv.y;
            KPt[d0 + 2][c] = kv.z;
            KPt[d0 + 3][c] = kv.w;
            *(float4*)&Vs[r][d0] = *(const float4*)&vt[r * HD + d0];
        }
        __syncthreads();

        // S = (Q*scale) K^T  (rows ty*4+i, cols tx*4+j)
        float acc[4][4];
#pragma unroll
        for (int i = 0; i < 4; i++)
#pragma unroll
            for (int j = 0; j < 4; j++) acc[i][j] = 0.f;

#pragma unroll
        for (int dd = 0; dd < 64; dd++) {
            const int sw = (dd >> 2) << 2;
            float4 av = *(const float4*)&Qt[dd][(ty << 2) ^ sw];
            float4 bv = *(const float4*)&KPt[dd][(tx << 2) ^ sw];
            float a_[4] = {av.x, av.y, av.z, av.w};
            float b_[4] = {bv.x, bv.y, bv.z, bv.w};
#pragma unroll
            for (int i = 0; i < 4; i++)
#pragma unroll
                for (int j = 0; j < 4; j++) acc[i][j] += a_[i] * b_[j];
        }

        // Online softmax per row (reduce across the 16 tx lanes, width 16)
#pragma unroll
        for (int i = 0; i < 4; i++) {
            float rm = -1e30f;
#pragma unroll
            for (int j = 0; j < 4; j++) rm = fmaxf(rm, acc[i][j]);
#pragma unroll
            for (int off = 8; off; off >>= 1)
                rm = fmaxf(rm, __shfl_xor_sync(0xffffffffu, rm, off, 16));

            const float mn = fmaxf(m[i], rm);
            const float al = __expf(m[i] - mn);
            float rs = 0.f;
#pragma unroll
            for (int j = 0; j < 4; j++) {
                acc[i][j] = __expf(acc[i][j] - mn);
                rs += acc[i][j];
            }
#pragma unroll
            for (int off = 8; off; off >>= 1)
                rs += __shfl_xor_sync(0xffffffffu, rs, off, 16);

            l[i] = l[i] * al + rs;
            m[i] = mn;
#pragma unroll
            for (int j = 0; j < 4; j++) o[i][j] *= al;
        }

        __syncthreads();   // everyone done reading KPt as K^T

        // Stage P^T into KPt (swizzled): KPt[c][r ^ sw(c)]
#pragma unroll
        for (int j = 0; j < 4; j++) {
            const int c  = (tx << 2) + j;
            const int sw = tx << 2;           // ((c>>2)<<2)
#pragma unroll
            for (int i = 0; i < 4; i++)
                KPt[c][((ty << 2) + i) ^ sw] = acc[i][j];
        }
        __syncthreads();

        // O += P V   (rows ty*4+i, d-cols tx*4+j)
#pragma unroll
        for (int cv = 0; cv < 64; cv++) {
            const int sw = (cv >> 2) << 2;
            float4 av = *(const float4*)&KPt[cv][(ty << 2) ^ sw];
            float4 bv = *(const float4*)&Vs[cv][tx << 2];
            float a_[4] = {av.x, av.y, av.z, av.w};
            float b_[4] = {bv.x, bv.y, bv.z, bv.w};
#pragma unroll
            for (int i = 0; i < 4; i++)
#pragma unroll
                for (int j = 0; j < 4; j++) o[i][j] += a_[i] * b_[j];
        }
        __syncthreads();
    }

    // Epilogue: out[b,h,n,d] with bh == blockIdx.y
    float* op = out + ((size_t)bh * NSEQ + q0) * HD;
#pragma unroll
    for (int i = 0; i < 4; i++) {
        const float inv = 1.f / l[i];
        const int r = (ty << 2) + i;
        float4 v = make_float4(o[i][0] * inv, o[i][1] * inv,
                               o[i][2] * inv, o[i][3] * inv);
        *(float4*)&op[r * HD + (tx << 2)] = v;
    }
}

// ---------------------------------------------------------------------------
extern "C" void kernel_launch(void* const* d_in, const int* in_sizes, int n_in,
                              void* d_out, int out_size)
{
    const float* x = (const float*)d_in[0];   // [2, 2048, 1024]
    const float* w = (const float*)d_in[1];   // [1024, 3072]
    float* out = (float*)d_out;               // [2, 16, 2048, 64]

    (void)in_sizes; (void)n_in; (void)out_size;

    qkv_gemm_kernel<<<dim3(NOUT / 64, (BATCH * NSEQ) / 64), 256>>>(x, w);
    attn_kernel<<<dim3(NSEQ / 64, BH), 256>>>(out);
}